// round 16
// baseline (speedup 1.0000x reference)
#include <cuda_runtime.h>
#include <cuda_bf16.h>
#include <cuda_fp16.h>
#include <cstdint>

#define BB 4
#define QN 128
#define KN 1024
#define DD 512     // DQ == DK == DV
#define HH 256
#define NSPLIT 8
#define KSPLIT (KN / NSPLIT)   // 128
#define PSPLIT 2               // proj split-K
#define PKS (DD / PSPLIT)      // 256

#define MROWS (BB * QN + BB * KN)   // 4608 combined projection rows

// ---------------- Scratch (__device__ globals; no allocs allowed) ----------
__device__ float g_scores[BB * QN * KN];             // [512][1024] -> attn in place
__device__ float g_avp[NSPLIT][BB * QN * DD];        // AV split-K partials
__device__ float g_pp[PSPLIT][MROWS * HH];           // proj split-K partials (f32)

__device__ __half2 g_qp2[BB * QN * HH / 2];          // qp as h-paired half2
__device__ __half2 g_kp2[BB * KN * HH / 2];          // kp as h-paired half2

__device__ __nv_bfloat16 g_ab_hi[MROWS * DD];        // combined Q|K rows, bf16 hi
__device__ __nv_bfloat16 g_ab_lo[MROWS * DD];
__device__ __nv_bfloat16 g_wt_hi[2][HH * DD];        // W^T bf16 hi  [256][512]
__device__ __nv_bfloat16 g_wt_lo[2][HH * DD];

// ---------------------------------------------------------------------------
// HMMA helpers (baseline PTX, plain sm_103 target)
// ---------------------------------------------------------------------------
__device__ __forceinline__ uint32_t smem_u32(const void* p) {
    uint32_t a;
    asm("{ .reg .u64 t; cvta.to.shared.u64 t, %1; cvt.u32.u64 %0, t; }" : "=r"(a) : "l"(p));
    return a;
}
__device__ __forceinline__ void ldsm_x4(uint32_t& r0, uint32_t& r1, uint32_t& r2,
                                        uint32_t& r3, uint32_t addr) {
    asm volatile("ldmatrix.sync.aligned.m8n8.x4.shared.b16 {%0,%1,%2,%3}, [%4];"
                 : "=r"(r0), "=r"(r1), "=r"(r2), "=r"(r3) : "r"(addr));
}
__device__ __forceinline__ void mma_bf16(float* d, const uint32_t* a, const uint32_t* b) {
    asm volatile(
        "mma.sync.aligned.m16n8k16.row.col.f32.bf16.bf16.f32 "
        "{%0,%1,%2,%3}, {%4,%5,%6,%7}, {%8,%9}, {%0,%1,%2,%3};"
        : "+f"(d[0]), "+f"(d[1]), "+f"(d[2]), "+f"(d[3])
        : "r"(a[0]), "r"(a[1]), "r"(a[2]), "r"(a[3]), "r"(b[0]), "r"(b[1]));
}

// ---------------------------------------------------------------------------
// Conversion: queries|keys rows -> bf16 hi/lo (combined [4608][512])
// ---------------------------------------------------------------------------
__global__ __launch_bounds__(256) void conv_ab(
    const float* __restrict__ queries, const float* __restrict__ keys)
{
    const int i4 = blockIdx.x * 256 + threadIdx.x;
    const int QF4 = BB * QN * DD / 4;
    float4 v = (i4 < QF4) ? ((const float4*)queries)[i4]
                          : ((const float4*)keys)[i4 - QF4];
    float s[4] = {v.x, v.y, v.z, v.w};
    __nv_bfloat16 h[4], l[4];
    #pragma unroll
    for (int j = 0; j < 4; j++) {
        h[j] = __float2bfloat16(s[j]);
        l[j] = __float2bfloat16(s[j] - __bfloat162float(h[j]));
    }
    __nv_bfloat162* oh = (__nv_bfloat162*)g_ab_hi;
    __nv_bfloat162* ol = (__nv_bfloat162*)g_ab_lo;
    oh[i4 * 2 + 0] = __halves2bfloat162(h[0], h[1]);
    oh[i4 * 2 + 1] = __halves2bfloat162(h[2], h[3]);
    ol[i4 * 2 + 0] = __halves2bfloat162(l[0], l[1]);
    ol[i4 * 2 + 1] = __halves2bfloat162(l[2], l[3]);
}

// ---------------------------------------------------------------------------
// Conversion: W[512][256] -> W^T bf16 hi/lo [256][512] (Wq z=0, Wk z=1)
// ---------------------------------------------------------------------------
__global__ __launch_bounds__(256) void conv_w(
    const float* __restrict__ Wq, const float* __restrict__ Wk)
{
    const int mat = blockIdx.z;
    const float* W = mat ? Wk : Wq;
    const int kt = blockIdx.x * 32;
    const int nt = blockIdx.y * 32;
    __shared__ float t[32][33];

    const int tx = threadIdx.x & 31;
    const int ty = threadIdx.x >> 5;
    #pragma unroll
    for (int i = 0; i < 4; i++) {
        int r = ty + i * 8;
        t[r][tx] = W[(size_t)(kt + r) * HH + nt + tx];
    }
    __syncthreads();
    #pragma unroll
    for (int i = 0; i < 4; i++) {
        int n = ty + i * 8;
        float v = t[tx][n];
        __nv_bfloat16 h = __float2bfloat16(v);
        __nv_bfloat16 l = __float2bfloat16(v - __bfloat162float(h));
        g_wt_hi[mat][(size_t)(nt + n) * DD + kt + tx] = h;
        g_wt_lo[mat][(size_t)(nt + n) * DD + kt + tx] = l;
    }
}

// ---------------------------------------------------------------------------
// HMMA projection GEMM, split-K: [128,64] tile per CTA over a 256-wide k-half.
// grid (36, 4, 2) = 288 CTAs. 3-term bf16 hi/lo split. f32 partials to g_pp.
// ---------------------------------------------------------------------------
#define ASTRIDE 24    // bf16 units per smem row (48 B)

__global__ __launch_bounds__(256) void proj_hmma(const int* __restrict__ vlen)
{
    __shared__ __align__(16) __nv_bfloat16 sA[2][2][128 * ASTRIDE];
    __shared__ __align__(16) __nv_bfloat16 sB[2][2][64 * ASTRIDE];

    const int tid  = threadIdx.x;
    const int wid  = tid >> 5;
    const int lane = tid & 31;

    const int m0   = blockIdx.x * 128;
    const int n0   = blockIdx.y * 64;
    const int kbeg = blockIdx.z * PKS;          // 0 or 256

    const __nv_bfloat16* wt_hi;
    const __nv_bfloat16* wt_lo;
    if (m0 < BB * QN) {
        wt_hi = g_wt_hi[0]; wt_lo = g_wt_lo[0];
    } else {
        int mk = m0 - BB * QN;
        int b = mk >> 10;
        if ((mk & 1023) >= vlen[b]) return;
        wt_hi = g_wt_hi[1]; wt_lo = g_wt_lo[1];
    }
    float* C = g_pp[blockIdx.z];                // partial output [MROWS][HH]

    const int warp_m = wid & 3;
    const int warp_n = wid >> 2;

    const int arow  = tid >> 1;
    const int ahalf = tid & 1;
    const int brow  = (tid & 127) >> 1;
    const int bterm = tid >> 7;

    const int a_r  = (lane & 7) + ((lane >> 3) & 1) * 8;
    const int a_c  = (lane >> 4) * 8;
    const int b_r  = (lane & 7) + ((lane >> 4) & 1) * 8;
    const int b_c  = ((lane >> 3) & 1) * 8;

    float acc[2][4][4] = {};
    float4 pah, pal, pbx;

    const __nv_bfloat16* wsel = bterm ? wt_lo : wt_hi;

    pah = *(const float4*)&g_ab_hi[(size_t)(m0 + arow) * DD + kbeg + ahalf * 8];
    pal = *(const float4*)&g_ab_lo[(size_t)(m0 + arow) * DD + kbeg + ahalf * 8];
    pbx = *(const float4*)&wsel[(size_t)(n0 + brow) * DD + kbeg + ahalf * 8];
    *(float4*)&sA[0][0][arow * ASTRIDE + ahalf * 8] = pah;
    *(float4*)&sA[0][1][arow * ASTRIDE + ahalf * 8] = pal;
    *(float4*)&sB[0][bterm][brow * ASTRIDE + ahalf * 8] = pbx;
    __syncthreads();

    int buf = 0;
    #pragma unroll 1
    for (int c = 0; c < 16; c++) {              // 16 chunks of K=16 (256 total)
        if (c + 1 < 16) {
            int k0 = kbeg + (c + 1) * 16;
            pah = *(const float4*)&g_ab_hi[(size_t)(m0 + arow) * DD + k0 + ahalf * 8];
            pal = *(const float4*)&g_ab_lo[(size_t)(m0 + arow) * DD + k0 + ahalf * 8];
            pbx = *(const float4*)&wsel[(size_t)(n0 + brow) * DD + k0 + ahalf * 8];
        }

        uint32_t Ah[2][4], Al[2][4], Bh[4][2], Bl[4][2];
        #pragma unroll
        for (int mt = 0; mt < 2; mt++) {
            uint32_t ra = smem_u32(&sA[buf][0][(warp_m * 32 + mt * 16 + a_r) * ASTRIDE + a_c]);
            ldsm_x4(Ah[mt][0], Ah[mt][1], Ah[mt][2], Ah[mt][3], ra);
            uint32_t rl = smem_u32(&sA[buf][1][(warp_m * 32 + mt * 16 + a_r) * ASTRIDE + a_c]);
            ldsm_x4(Al[mt][0], Al[mt][1], Al[mt][2], Al[mt][3], rl);
        }
        #pragma unroll
        for (int p = 0; p < 2; p++) {
            uint32_t rb = smem_u32(&sB[buf][0][(warp_n * 32 + p * 16 + b_r) * ASTRIDE + b_c]);
            ldsm_x4(Bh[p * 2][0], Bh[p * 2][1], Bh[p * 2 + 1][0], Bh[p * 2 + 1][1], rb);
            uint32_t rc = smem_u32(&sB[buf][1][(warp_n * 32 + p * 16 + b_r) * ASTRIDE + b_c]);
            ldsm_x4(Bl[p * 2][0], Bl[p * 2][1], Bl[p * 2 + 1][0], Bl[p * 2 + 1][1], rc);
        }
        #pragma unroll
        for (int mt = 0; mt < 2; mt++)
            #pragma unroll
            for (int nt = 0; nt < 4; nt++) {
                mma_bf16(acc[mt][nt], Ah[mt], Bh[nt]);
                mma_bf16(acc[mt][nt], Ah[mt], Bl[nt]);
                mma_bf16(acc[mt][nt], Al[mt], Bh[nt]);
            }

        if (c + 1 < 16) {
            int nb = buf ^ 1;
            *(float4*)&sA[nb][0][arow * ASTRIDE + ahalf * 8] = pah;
            *(float4*)&sA[nb][1][arow * ASTRIDE + ahalf * 8] = pal;
            *(float4*)&sB[nb][bterm][brow * ASTRIDE + ahalf * 8] = pbx;
            __syncthreads();
            buf = nb;
        }
    }

    // epilogue: f32 partials
    const int tq = lane >> 2;
    const int tr = lane & 3;
    #pragma unroll
    for (int mt = 0; mt < 2; mt++)
        #pragma unroll
        for (int nt = 0; nt < 4; nt++) {
            int m = m0 + warp_m * 32 + mt * 16 + tq;
            int n = n0 + warp_n * 32 + nt * 8 + tr * 2;
            *(float2*)&C[(size_t)m * HH + n] =
                make_float2(acc[mt][nt][0], acc[mt][nt][1]);
            *(float2*)&C[(size_t)(m + 8) * HH + n] =
                make_float2(acc[mt][nt][2], acc[mt][nt][3]);
        }
}

// ---------------------------------------------------------------------------
// Sum proj split-K partials + pack to h-paired half2 (qp2 / kp2).
// WIDE version: 8 halves per thread (2x float4 per partial, one 16B store),
// key rows beyond valid_len skipped entirely (their stale g_kp2 contents are
// deterministic and only feed masked score positions).
// grid 576 x 256 (147456 groups of 8).
// ---------------------------------------------------------------------------
__global__ __launch_bounds__(256) void proj_pack(const int* __restrict__ vlen)
{
    const int idx = blockIdx.x * 256 + threadIdx.x;   // 8-half group index
    const int row = idx >> 5;                         // 0..4607 (32 groups/row)
    const int g   = idx & 31;

    if (row >= BB * QN) {                             // key row: vlen skip
        int mk = row - BB * QN;
        int b = mk >> 10;
        if ((mk & 1023) >= vlen[b]) return;
    }

    const size_t base = (size_t)row * HH + g * 8;     // float index
    float4 a0 = *(const float4*)&g_pp[0][base];
    float4 a1 = *(const float4*)&g_pp[0][base + 4];
    float4 b0 = *(const float4*)&g_pp[1][base];
    float4 b1 = *(const float4*)&g_pp[1][base + 4];

    __half2 h[4];
    h[0] = __floats2half2_rn(a0.x + b0.x, a0.y + b0.y);
    h[1] = __floats2half2_rn(a0.z + b0.z, a0.w + b0.w);
    h[2] = __floats2half2_rn(a1.x + b1.x, a1.y + b1.y);
    h[3] = __floats2half2_rn(a1.z + b1.z, a1.w + b1.w);

    const int QROWS = BB * QN;
    __half2* dst = (row < QROWS)
        ? (g_qp2 + (size_t)row * (HH / 2) + g * 4)
        : (g_kp2 + (size_t)(row - QROWS) * (HH / 2) + g * 4);
    *(float4*)dst = *(float4*)h;                      // 16B store (4 half2)
}

// ---------------------------------------------------------------------------
// Scores (f16x2, wide LDS, 16-q tile): block 512 = 16 warps, one q per warp,
// lanes cover 64 k (2 adjacent per lane). grid (k 16, q 8, b 4).
// ---------------------------------------------------------------------------
__global__ __launch_bounds__(512, 2) void scores_kernel(
    const float* __restrict__ wv, const int* __restrict__ vlen)
{
    const int b  = blockIdx.z;
    const int q0 = blockIdx.y * 16;
    const int k0 = blockIdx.x * 64;
    const int vl = vlen[b];
    if (k0 >= vl) return;

    __shared__ __align__(16) __half2 qs2[16][128];  // 8 KB
    __shared__ __align__(16) float   wvf[256];      // 1 KB
    __shared__ __align__(16) __half2 kst[128][66];  // ~33.8 KB transposed

    const int tid  = threadIdx.x;
    const int lane = tid & 31;
    const int w    = tid >> 5;

    const uint32_t* qp2 = (const uint32_t*)(g_qp2 + (size_t)(b * QN + q0) * 128);
    #pragma unroll
    for (int i = 0; i < 4; i++)
        ((uint32_t*)qs2)[tid + i * 512] = qp2[tid + i * 512];
    if (tid < 64) ((float4*)wvf)[tid] = ((const float4*)wv)[tid];

    {
        const __half2* kp2 = g_kp2 + (size_t)(b * KN + k0) * 128;
        const int q8 = tid & 3;
        const int kk = (tid >> 2) & 63;
        const int ub = tid >> 8;               // 0/1
        #pragma unroll
        for (int j = 0; j < 4; j++) {
            int hpq = q8 + (ub * 4 + j) * 4;   // 0..31
            float4 v = ((const float4*)(kp2 + (size_t)kk * 128))[hpq];
            const __half2* pv = (const __half2*)&v;
            #pragma unroll
            for (int r = 0; r < 4; r++)
                kst[hpq * 4 + r][kk] = pv[r];
        }
    }
    __syncthreads();

    const int q = w;
    float a00 = 0.f, a01 = 0.f, a10 = 0.f, a11 = 0.f;
    #pragma unroll 4
    for (int hp = 0; hp < 128; hp += 2) {
        uint2  qp_ = *(const uint2*)&qs2[q][hp];
        float4 wq  = *(const float4*)&wvf[hp * 2];
        float2 kp0 = *(const float2*)&kst[hp][2 * lane];
        float2 kp1 = *(const float2*)&kst[hp + 1][2 * lane];
        __half2 qv0 = *(__half2*)&qp_.x;
        __half2 qv1 = *(__half2*)&qp_.y;
        const __half2* k0v = (const __half2*)&kp0;
        const __half2* k1v = (const __half2*)&kp1;

        __half2 x00 = __hadd2(qv0, k0v[0]);
        __half2 x01 = __hadd2(qv0, k0v[1]);
        __half2 x10 = __hadd2(qv1, k1v[0]);
        __half2 x11 = __hadd2(qv1, k1v[1]);
        uint32_t t00, t01, t10, t11;
        asm("tanh.approx.f16x2 %0, %1;" : "=r"(t00) : "r"(*(uint32_t*)&x00));
        asm("tanh.approx.f16x2 %0, %1;" : "=r"(t01) : "r"(*(uint32_t*)&x01));
        asm("tanh.approx.f16x2 %0, %1;" : "=r"(t10) : "r"(*(uint32_t*)&x10));
        asm("tanh.approx.f16x2 %0, %1;" : "=r"(t11) : "r"(*(uint32_t*)&x11));
        float2 f00 = __half22float2(*(__half2*)&t00);
        float2 f01 = __half22float2(*(__half2*)&t01);
        float2 f10 = __half22float2(*(__half2*)&t10);
        float2 f11 = __half22float2(*(__half2*)&t11);
        a00 = fmaf(wq.x, f00.x, a00); a00 = fmaf(wq.y, f00.y, a00);
        a01 = fmaf(wq.x, f01.x, a01); a01 = fmaf(wq.y, f01.y, a01);
        a10 = fmaf(wq.z, f10.x, a10); a10 = fmaf(wq.w, f10.y, a10);
        a11 = fmaf(wq.z, f11.x, a11); a11 = fmaf(wq.w, f11.y, a11);
    }
    size_t row = (size_t)(b * QN + q0 + q) * KN;
    *(float2*)&g_scores[row + k0 + 2 * lane] = make_float2(a00 + a10, a01 + a11);
}

// ---------------------------------------------------------------------------
// Softmax in place (masked -> exact 0). One warp per row, float4 I/O.
// ---------------------------------------------------------------------------
__global__ __launch_bounds__(128) void softmax_kernel(const int* __restrict__ vlen)
{
    const int row  = blockIdx.x * 4 + (threadIdx.x >> 5);
    const int lane = threadIdx.x & 31;
    const int b    = row >> 7;
    const int vl   = vlen[b];
    float* s = g_scores + (size_t)row * KN;

    float4 v4[8];
    float mx = -1e30f;
    #pragma unroll
    for (int i = 0; i < 8; i++) {
        int kk4 = lane + i * 32;               // float4 index
        float4 v = ((const float4*)s)[kk4];
        int kk = kk4 * 4;
        v.x = (kk + 0 < vl) ? v.x : -1e30f;
        v.y = (kk + 1 < vl) ? v.y : -1e30f;
        v.z = (kk + 2 < vl) ? v.z : -1e30f;
        v.w = (kk + 3 < vl) ? v.w : -1e30f;
        v4[i] = v;
        mx = fmaxf(mx, fmaxf(fmaxf(v.x, v.y), fmaxf(v.z, v.w)));
    }
    #pragma unroll
    for (int o = 16; o; o >>= 1) mx = fmaxf(mx, __shfl_xor_sync(0xffffffffu, mx, o));

    float sum = 0.f;
    #pragma unroll
    for (int i = 0; i < 8; i++) {
        float4 v = v4[i];
        v.x = (v.x > -1e29f) ? __expf(v.x - mx) : 0.f;
        v.y = (v.y > -1e29f) ? __expf(v.y - mx) : 0.f;
        v.z = (v.z > -1e29f) ? __expf(v.z - mx) : 0.f;
        v.w = (v.w > -1e29f) ? __expf(v.w - mx) : 0.f;
        v4[i] = v;
        sum += (v.x + v.y) + (v.z + v.w);
    }
    #pragma unroll
    for (int o = 16; o; o >>= 1) sum += __shfl_xor_sync(0xffffffffu, sum, o);

    float r = 1.f / sum;
    #pragma unroll
    for (int i = 0; i < 8; i++) {
        float4 v = v4[i];
        v.x *= r; v.y *= r; v.z *= r; v.w *= r;
        ((float4*)s)[lane + i * 32] = v;
    }
}

// ---------------------------------------------------------------------------
// AV GEMM split-K (measured-best fp32 config: 256 thr, 4x4/thread, pipelined)
// ---------------------------------------------------------------------------
struct GemmSmem {
    float As[2][16][68];
    float Bs[2][16][68];
};

__global__ __launch_bounds__(256) void av_gemm(
    const float* __restrict__ V, const int* __restrict__ vlen)
{
    const int bz = blockIdx.z;
    const int b  = bz >> 3;
    const int s  = bz & 7;
    const int m0 = blockIdx.x * 64;
    const int n0 = blockIdx.y * 64;
    const int vl = vlen[b];
    const int kcap = min(KN, (vl + 15) & ~15);

    const int kbeg = s * KSPLIT;
    const int kend = min(kbeg + KSPLIT, kcap);
    if (kbeg >= kend) return;

    const float* __restrict__ A  = g_scores + (size_t)b * QN * KN;
    const float* __restrict__ Bv = V + (size_t)b * KN * DD;
    float* __restrict__ C        = g_avp[s] + (size_t)b * QN * DD;

    __shared__ __align__(16) GemmSmem sm;

    const int tid = threadIdx.x;
    const int tx = tid & 15;
    const int ty = tid >> 4;
    const int arow = tid >> 2;
    const int ac4  = tid & 3;
    const int bn4  = tid & 15;
    const int bkk  = tid >> 4;

    const int ntile = (kend - kbeg) >> 4;

    float acc[4][4] = {};
    float4 pa, pb;

    pa = *(const float4*)&A[(size_t)(m0 + arow) * KN + kbeg + ac4 * 4];
    pb = *(const float4*)&Bv[(size_t)(kbeg + bkk) * DD + n0 + bn4 * 4];
    sm.As[0][ac4 * 4 + 0][arow] = pa.x;
    sm.As[0][ac4 * 4 + 1][arow] = pa.y;
    sm.As[0][ac4 * 4 + 2][arow] = pa.z;
    sm.As[0][ac4 * 4 + 3][arow] = pa.w;
    *(float4*)&sm.Bs[0][bkk][bn4 * 4] = pb;
    __syncthreads();

    int buf = 0;
    for (int t = 0; t < ntile; t++) {
        if (t + 1 < ntile) {
            int k0 = kbeg + (t + 1) * 16;
            pa = *(const float4*)&A[(size_t)(m0 + arow) * KN + k0 + ac4 * 4];
            pb = *(const float4*)&Bv[(size_t)(k0 + bkk) * DD + n0 + bn4 * 4];
        }
        #pragma unroll
        for (int kk = 0; kk < 16; kk++) {
            float4 a = *(const float4*)&sm.As[buf][kk][ty * 4];
            float4 bq = *(const float4*)&sm.Bs[buf][kk][tx * 4];
            float av[4] = {a.x, a.y, a.z, a.w};
            float bv2[4] = {bq.x, bq.y, bq.z, bq.w};
            #pragma unroll
            for (int i = 0; i < 4; i++)
                #pragma unroll
                for (int j = 0; j < 4; j++)
                    acc[i][j] = fmaf(av[i], bv2[j], acc[i][j]);
        }
        if (t + 1 < ntile) {
            int nb = buf ^ 1;
            sm.As[nb][ac4 * 4 + 0][arow] = pa.x;
            sm.As[nb][ac4 * 4 + 1][arow] = pa.y;
            sm.As[nb][ac4 * 4 + 2][arow] = pa.z;
            sm.As[nb][ac4 * 4 + 3][arow] = pa.w;
            *(float4*)&sm.Bs[nb][bkk][bn4 * 4] = pb;
            __syncthreads();
            buf = nb;
        }
    }

    #pragma unroll
    for (int i = 0; i < 4; i++) {
        float4 o = make_float4(acc[i][0], acc[i][1], acc[i][2], acc[i][3]);
        *(float4*)&C[(size_t)(m0 + ty * 4 + i) * DD + n0 + tx * 4] = o;
    }
}

// ---------------------------------------------------------------------------
// Reduce AV split-K partials into out.
// ---------------------------------------------------------------------------
__global__ __launch_bounds__(256) void av_reduce(
    float* __restrict__ out, const int* __restrict__ vlen)
{
    const int idx = blockIdx.x * 256 + threadIdx.x;
    const int perB = QN * DD / 4;
    const int b = idx / perB;
    const int vl = vlen[b];
    const int ns = min(NSPLIT, (vl + KSPLIT - 1) / KSPLIT);

    float4 acc = ((const float4*)g_avp[0])[idx];
    for (int s = 1; s < ns; s++) {
        float4 p = ((const float4*)g_avp[s])[idx];
        acc.x += p.x; acc.y += p.y; acc.z += p.z; acc.w += p.w;
    }
    ((float4*)out)[idx] = acc;
}

// ---------------------------------------------------------------------------
extern "C" void kernel_launch(void* const* d_in, const int* in_sizes, int n_in,
                              void* d_out, int out_size)
{
    (void)in_sizes; (void)n_in; (void)out_size;
    const float* queries = (const float*)d_in[0];   // [4,128,512]
    const float* keys    = (const float*)d_in[1];   // [4,1024,512]
    const float* values  = (const float*)d_in[2];   // [4,1024,512]
    const int*   vlen    = (const int*)d_in[3];     // [4]
    const float* Wq      = (const float*)d_in[4];   // [512,256]
    const float* Wk      = (const float*)d_in[5];   // [512,256]
    const float* wv      = (const float*)d_in[6];   // [256]
    float* out = (float*)d_out;                     // [4,128,512]

    conv_ab<<<2304, 256>>>(queries, keys);
    conv_w<<<dim3(16, 8, 2), 256>>>(Wq, Wk);
    proj_hmma<<<dim3(36, 4, PSPLIT), 256>>>(vlen);
    proj_pack<<<576, 256>>>(vlen);
    scores_kernel<<<dim3(16, 8, 4), 512>>>(wv, vlen);
    softmax_kernel<<<128, 128>>>(vlen);
    av_gemm<<<dim3(2, 8, BB * NSPLIT), 256>>>(values, vlen);
    av_reduce<<<256, 256>>>(out, vlen);
}

// round 17
// speedup vs baseline: 1.0021x; 1.0021x over previous
#include <cuda_runtime.h>
#include <cuda_bf16.h>
#include <cuda_fp16.h>
#include <cstdint>

#define BB 4
#define QN 128
#define KN 1024
#define DD 512     // DQ == DK == DV
#define HH 256
#define NSPLIT 8
#define KSPLIT (KN / NSPLIT)   // 128

#define MROWS (BB * QN + BB * KN)   // 4608 combined projection rows

// ---------------- Scratch (__device__ globals; no allocs allowed) ----------
__device__ float g_scores[BB * QN * KN];             // [512][1024] -> attn in place
__device__ float g_avp[NSPLIT][BB * QN * DD];        // AV split-K partials

__device__ __half2 g_qp2[BB * QN * HH / 2];          // qp as h-paired half2
__device__ __half2 g_kp2[BB * KN * HH / 2];          // kp as h-paired half2

__device__ __nv_bfloat16 g_ab_hi[MROWS * DD];        // combined Q|K rows, bf16 hi
__device__ __nv_bfloat16 g_ab_lo[MROWS * DD];
__device__ __nv_bfloat16 g_wt_hi[2][HH * DD];        // W^T bf16 hi  [256][512]
__device__ __nv_bfloat16 g_wt_lo[2][HH * DD];

// ---------------------------------------------------------------------------
// HMMA helpers (baseline PTX, plain sm_103 target)
// ---------------------------------------------------------------------------
__device__ __forceinline__ uint32_t smem_u32(const void* p) {
    uint32_t a;
    asm("{ .reg .u64 t; cvta.to.shared.u64 t, %1; cvt.u32.u64 %0, t; }" : "=r"(a) : "l"(p));
    return a;
}
__device__ __forceinline__ void ldsm_x4(uint32_t& r0, uint32_t& r1, uint32_t& r2,
                                        uint32_t& r3, uint32_t addr) {
    asm volatile("ldmatrix.sync.aligned.m8n8.x4.shared.b16 {%0,%1,%2,%3}, [%4];"
                 : "=r"(r0), "=r"(r1), "=r"(r2), "=r"(r3) : "r"(addr));
}
__device__ __forceinline__ void mma_bf16(float* d, const uint32_t* a, const uint32_t* b) {
    asm volatile(
        "mma.sync.aligned.m16n8k16.row.col.f32.bf16.bf16.f32 "
        "{%0,%1,%2,%3}, {%4,%5,%6,%7}, {%8,%9}, {%0,%1,%2,%3};"
        : "+f"(d[0]), "+f"(d[1]), "+f"(d[2]), "+f"(d[3])
        : "r"(a[0]), "r"(a[1]), "r"(a[2]), "r"(a[3]), "r"(b[0]), "r"(b[1]));
}

// ---------------------------------------------------------------------------
// Conversion: queries|keys rows -> bf16 hi/lo (combined [4608][512])
// ---------------------------------------------------------------------------
__global__ __launch_bounds__(256) void conv_ab(
    const float* __restrict__ queries, const float* __restrict__ keys)
{
    const int i4 = blockIdx.x * 256 + threadIdx.x;
    const int QF4 = BB * QN * DD / 4;
    float4 v = (i4 < QF4) ? ((const float4*)queries)[i4]
                          : ((const float4*)keys)[i4 - QF4];
    float s[4] = {v.x, v.y, v.z, v.w};
    __nv_bfloat16 h[4], l[4];
    #pragma unroll
    for (int j = 0; j < 4; j++) {
        h[j] = __float2bfloat16(s[j]);
        l[j] = __float2bfloat16(s[j] - __bfloat162float(h[j]));
    }
    __nv_bfloat162* oh = (__nv_bfloat162*)g_ab_hi;
    __nv_bfloat162* ol = (__nv_bfloat162*)g_ab_lo;
    oh[i4 * 2 + 0] = __halves2bfloat162(h[0], h[1]);
    oh[i4 * 2 + 1] = __halves2bfloat162(h[2], h[3]);
    ol[i4 * 2 + 0] = __halves2bfloat162(l[0], l[1]);
    ol[i4 * 2 + 1] = __halves2bfloat162(l[2], l[3]);
}

// ---------------------------------------------------------------------------
// Conversion: W[512][256] -> W^T bf16 hi/lo [256][512] (Wq z=0, Wk z=1)
// ---------------------------------------------------------------------------
__global__ __launch_bounds__(256) void conv_w(
    const float* __restrict__ Wq, const float* __restrict__ Wk)
{
    const int mat = blockIdx.z;
    const float* W = mat ? Wk : Wq;
    const int kt = blockIdx.x * 32;
    const int nt = blockIdx.y * 32;
    __shared__ float t[32][33];

    const int tx = threadIdx.x & 31;
    const int ty = threadIdx.x >> 5;
    #pragma unroll
    for (int i = 0; i < 4; i++) {
        int r = ty + i * 8;
        t[r][tx] = W[(size_t)(kt + r) * HH + nt + tx];
    }
    __syncthreads();
    #pragma unroll
    for (int i = 0; i < 4; i++) {
        int n = ty + i * 8;
        float v = t[tx][n];
        __nv_bfloat16 h = __float2bfloat16(v);
        __nv_bfloat16 l = __float2bfloat16(v - __bfloat162float(h));
        g_wt_hi[mat][(size_t)(nt + n) * DD + kt + tx] = h;
        g_wt_lo[mat][(size_t)(nt + n) * DD + kt + tx] = l;
    }
}

// ---------------------------------------------------------------------------
// HMMA projection GEMM, FUSED intra-CTA split-K: 512 threads = 2 groups of
// 8 warps; group g covers k in [g*256, g*256+256). Per-tile smem reduce +
// half2 pack in the epilogue — no global partials, no pack kernel.
// grid (36, 4) x 512, dynamic smem 72 KB (16 warps/SM, reg-capped 1 CTA/SM).
// ---------------------------------------------------------------------------
#define ASTRIDE 24    // bf16 units per smem row (48 B)
#define SA_GRP (2 * 2 * 128 * ASTRIDE)     // bf16 per group (buf,term,128 rows)
#define SB_GRP (2 * 2 * 64 * ASTRIDE)
#define SA_BYTES (2 * SA_GRP * 2)          // 49152
#define SB_BYTES (2 * SB_GRP * 2)          // 24576
#define PROJ_SMEM (SA_BYTES + SB_BYTES)    // 73728

__global__ __launch_bounds__(512) void proj_hmma(const int* __restrict__ vlen)
{
    extern __shared__ __align__(16) char smem[];
    __nv_bfloat16* sAg = (__nv_bfloat16*)smem;              // [g][buf][term][3072]
    __nv_bfloat16* sBg = (__nv_bfloat16*)(smem + SA_BYTES); // [g][buf][term][1536]
    float* sred = (float*)smem;                             // alias (epilogue)

    const int tid  = threadIdx.x;
    const int wid  = tid >> 5;
    const int lane = tid & 31;
    const int g    = tid >> 8;                  // k-half group 0/1
    const int wg   = wid & 7;                   // warp within group

    const int m0   = blockIdx.x * 128;
    const int n0   = blockIdx.y * 64;
    const int kbeg = g * 256;

    const __nv_bfloat16* wt_hi;
    const __nv_bfloat16* wt_lo;
    __half2* C2;
    int crow;
    if (m0 < BB * QN) {
        wt_hi = g_wt_hi[0]; wt_lo = g_wt_lo[0]; C2 = g_qp2; crow = m0;
    } else {
        int mk = m0 - BB * QN;
        int b = mk >> 10;
        if ((mk & 1023) >= vlen[b]) return;
        wt_hi = g_wt_hi[1]; wt_lo = g_wt_lo[1]; C2 = g_kp2; crow = mk;
    }

    const int warp_m = wg & 3;
    const int warp_n = wg >> 2;

    // per-group load mapping (t = thread within group)
    const int t     = tid & 255;
    const int arow  = t >> 1;
    const int ahalf = t & 1;
    const int brow  = (t & 127) >> 1;
    const int bterm = t >> 7;

    const int a_r  = (lane & 7) + ((lane >> 3) & 1) * 8;
    const int a_c  = (lane >> 4) * 8;
    const int b_r  = (lane & 7) + ((lane >> 4) & 1) * 8;
    const int b_c  = ((lane >> 3) & 1) * 8;

    float acc[2][4][4] = {};
    float4 pah, pal, pbx;

    const __nv_bfloat16* wsel = bterm ? wt_lo : wt_hi;

    // smem base helpers (group-local)
    __nv_bfloat16* sA = sAg + g * SA_GRP;       // [buf][term][128*24]
    __nv_bfloat16* sB = sBg + g * SB_GRP;       // [buf][term][64*24]

    pah = *(const float4*)&g_ab_hi[(size_t)(m0 + arow) * DD + kbeg + ahalf * 8];
    pal = *(const float4*)&g_ab_lo[(size_t)(m0 + arow) * DD + kbeg + ahalf * 8];
    pbx = *(const float4*)&wsel[(size_t)(n0 + brow) * DD + kbeg + ahalf * 8];
    *(float4*)&sA[(0 * 2 + 0) * 3072 + arow * ASTRIDE + ahalf * 8] = pah;
    *(float4*)&sA[(0 * 2 + 1) * 3072 + arow * ASTRIDE + ahalf * 8] = pal;
    *(float4*)&sB[(0 * 2 + bterm) * 1536 + brow * ASTRIDE + ahalf * 8] = pbx;
    __syncthreads();

    int buf = 0;
    #pragma unroll 1
    for (int c = 0; c < 16; c++) {              // 16 chunks of K=16 (256 per group)
        if (c + 1 < 16) {
            int k0 = kbeg + (c + 1) * 16;
            pah = *(const float4*)&g_ab_hi[(size_t)(m0 + arow) * DD + k0 + ahalf * 8];
            pal = *(const float4*)&g_ab_lo[(size_t)(m0 + arow) * DD + k0 + ahalf * 8];
            pbx = *(const float4*)&wsel[(size_t)(n0 + brow) * DD + k0 + ahalf * 8];
        }

        uint32_t Ah[2][4], Al[2][4], Bh[4][2], Bl[4][2];
        #pragma unroll
        for (int mt = 0; mt < 2; mt++) {
            uint32_t ra = smem_u32(&sA[(buf * 2 + 0) * 3072 + (warp_m * 32 + mt * 16 + a_r) * ASTRIDE + a_c]);
            ldsm_x4(Ah[mt][0], Ah[mt][1], Ah[mt][2], Ah[mt][3], ra);
            uint32_t rl = smem_u32(&sA[(buf * 2 + 1) * 3072 + (warp_m * 32 + mt * 16 + a_r) * ASTRIDE + a_c]);
            ldsm_x4(Al[mt][0], Al[mt][1], Al[mt][2], Al[mt][3], rl);
        }
        #pragma unroll
        for (int p = 0; p < 2; p++) {
            uint32_t rb = smem_u32(&sB[(buf * 2 + 0) * 1536 + (warp_n * 32 + p * 16 + b_r) * ASTRIDE + b_c]);
            ldsm_x4(Bh[p * 2][0], Bh[p * 2][1], Bh[p * 2 + 1][0], Bh[p * 2 + 1][1], rb);
            uint32_t rc = smem_u32(&sB[(buf * 2 + 1) * 1536 + (warp_n * 32 + p * 16 + b_r) * ASTRIDE + b_c]);
            ldsm_x4(Bl[p * 2][0], Bl[p * 2][1], Bl[p * 2 + 1][0], Bl[p * 2 + 1][1], rc);
        }
        #pragma unroll
        for (int mt = 0; mt < 2; mt++)
            #pragma unroll
            for (int nt = 0; nt < 4; nt++) {
                mma_bf16(acc[mt][nt], Ah[mt], Bh[nt]);
                mma_bf16(acc[mt][nt], Ah[mt], Bl[nt]);
                mma_bf16(acc[mt][nt], Al[mt], Bh[nt]);
            }

        if (c + 1 < 16) {
            int nb = buf ^ 1;
            *(float4*)&sA[(nb * 2 + 0) * 3072 + arow * ASTRIDE + ahalf * 8] = pah;
            *(float4*)&sA[(nb * 2 + 1) * 3072 + arow * ASTRIDE + ahalf * 8] = pal;
            *(float4*)&sB[(nb * 2 + bterm) * 1536 + brow * ASTRIDE + ahalf * 8] = pbx;
            __syncthreads();
            buf = nb;
        }
    }

    // ---- fused reduce + pack epilogue ----
    // Layouts are lane-identical across groups: group 1 dumps its 32 accs
    // into padded smem; group 0 adds and packs half2.
    __syncthreads();                            // all sA/sB reads done (alias!)
    if (g == 1) {
        float* dst = &sred[((wg * 32) + lane) * 33];
        #pragma unroll
        for (int mt = 0; mt < 2; mt++)
            #pragma unroll
            for (int nt = 0; nt < 4; nt++)
                #pragma unroll
                for (int j = 0; j < 4; j++)
                    dst[mt * 16 + nt * 4 + j] = acc[mt][nt][j];
    }
    __syncthreads();
    if (g == 0) {
        const float* src = &sred[((wg * 32) + lane) * 33];
        const int tq = lane >> 2;
        const int tr = lane & 3;
        #pragma unroll
        for (int mt = 0; mt < 2; mt++)
            #pragma unroll
            for (int nt = 0; nt < 4; nt++) {
                float v0 = acc[mt][nt][0] + src[mt * 16 + nt * 4 + 0];
                float v1 = acc[mt][nt][1] + src[mt * 16 + nt * 4 + 1];
                float v2 = acc[mt][nt][2] + src[mt * 16 + nt * 4 + 2];
                float v3 = acc[mt][nt][3] + src[mt * 16 + nt * 4 + 3];
                int m = crow + warp_m * 32 + mt * 16 + tq;
                int hp = (n0 + warp_n * 32 + nt * 8 + tr * 2) >> 1;
                C2[(size_t)m * (HH / 2) + hp]       = __floats2half2_rn(v0, v1);
                C2[(size_t)(m + 8) * (HH / 2) + hp] = __floats2half2_rn(v2, v3);
            }
    }
}

// ---------------------------------------------------------------------------
// Scores (f16x2, wide LDS, 16-q tile): block 512 = 16 warps, one q per warp,
// lanes cover 64 k (2 adjacent per lane). grid (k 16, q 8, b 4).
// ---------------------------------------------------------------------------
__global__ __launch_bounds__(512, 2) void scores_kernel(
    const float* __restrict__ wv, const int* __restrict__ vlen)
{
    const int b  = blockIdx.z;
    const int q0 = blockIdx.y * 16;
    const int k0 = blockIdx.x * 64;
    const int vl = vlen[b];
    if (k0 >= vl) return;

    __shared__ __align__(16) __half2 qs2[16][128];  // 8 KB
    __shared__ __align__(16) float   wvf[256];      // 1 KB
    __shared__ __align__(16) __half2 kst[128][66];  // ~33.8 KB transposed

    const int tid  = threadIdx.x;
    const int lane = tid & 31;
    const int w    = tid >> 5;

    const uint32_t* qp2 = (const uint32_t*)(g_qp2 + (size_t)(b * QN + q0) * 128);
    #pragma unroll
    for (int i = 0; i < 4; i++)
        ((uint32_t*)qs2)[tid + i * 512] = qp2[tid + i * 512];
    if (tid < 64) ((float4*)wvf)[tid] = ((const float4*)wv)[tid];

    {
        const __half2* kp2 = g_kp2 + (size_t)(b * KN + k0) * 128;
        const int q8 = tid & 3;
        const int kk = (tid >> 2) & 63;
        const int ub = tid >> 8;               // 0/1
        #pragma unroll
        for (int j = 0; j < 4; j++) {
            int hpq = q8 + (ub * 4 + j) * 4;   // 0..31
            float4 v = ((const float4*)(kp2 + (size_t)kk * 128))[hpq];
            const __half2* pv = (const __half2*)&v;
            #pragma unroll
            for (int r = 0; r < 4; r++)
                kst[hpq * 4 + r][kk] = pv[r];
        }
    }
    __syncthreads();

    const int q = w;
    float a00 = 0.f, a01 = 0.f, a10 = 0.f, a11 = 0.f;
    #pragma unroll 4
    for (int hp = 0; hp < 128; hp += 2) {
        uint2  qp_ = *(const uint2*)&qs2[q][hp];
        float4 wq  = *(const float4*)&wvf[hp * 2];
        float2 kp0 = *(const float2*)&kst[hp][2 * lane];
        float2 kp1 = *(const float2*)&kst[hp + 1][2 * lane];
        __half2 qv0 = *(__half2*)&qp_.x;
        __half2 qv1 = *(__half2*)&qp_.y;
        const __half2* k0v = (const __half2*)&kp0;
        const __half2* k1v = (const __half2*)&kp1;

        __half2 x00 = __hadd2(qv0, k0v[0]);
        __half2 x01 = __hadd2(qv0, k0v[1]);
        __half2 x10 = __hadd2(qv1, k1v[0]);
        __half2 x11 = __hadd2(qv1, k1v[1]);
        uint32_t t00, t01, t10, t11;
        asm("tanh.approx.f16x2 %0, %1;" : "=r"(t00) : "r"(*(uint32_t*)&x00));
        asm("tanh.approx.f16x2 %0, %1;" : "=r"(t01) : "r"(*(uint32_t*)&x01));
        asm("tanh.approx.f16x2 %0, %1;" : "=r"(t10) : "r"(*(uint32_t*)&x10));
        asm("tanh.approx.f16x2 %0, %1;" : "=r"(t11) : "r"(*(uint32_t*)&x11));
        float2 f00 = __half22float2(*(__half2*)&t00);
        float2 f01 = __half22float2(*(__half2*)&t01);
        float2 f10 = __half22float2(*(__half2*)&t10);
        float2 f11 = __half22float2(*(__half2*)&t11);
        a00 = fmaf(wq.x, f00.x, a00); a00 = fmaf(wq.y, f00.y, a00);
        a01 = fmaf(wq.x, f01.x, a01); a01 = fmaf(wq.y, f01.y, a01);
        a10 = fmaf(wq.z, f10.x, a10); a10 = fmaf(wq.w, f10.y, a10);
        a11 = fmaf(wq.z, f11.x, a11); a11 = fmaf(wq.w, f11.y, a11);
    }
    size_t row = (size_t)(b * QN + q0 + q) * KN;
    *(float2*)&g_scores[row + k0 + 2 * lane] = make_float2(a00 + a10, a01 + a11);
}

// ---------------------------------------------------------------------------
// Softmax in place (masked -> exact 0). One warp per row, float4 I/O.
// ---------------------------------------------------------------------------
__global__ __launch_bounds__(128) void softmax_kernel(const int* __restrict__ vlen)
{
    const int row  = blockIdx.x * 4 + (threadIdx.x >> 5);
    const int lane = threadIdx.x & 31;
    const int b    = row >> 7;
    const int vl   = vlen[b];
    float* s = g_scores + (size_t)row * KN;

    float4 v4[8];
    float mx = -1e30f;
    #pragma unroll
    for (int i = 0; i < 8; i++) {
        int kk4 = lane + i * 32;               // float4 index
        float4 v = ((const float4*)s)[kk4];
        int kk = kk4 * 4;
        v.x = (kk + 0 < vl) ? v.x : -1e30f;
        v.y = (kk + 1 < vl) ? v.y : -1e30f;
        v.z = (kk + 2 < vl) ? v.z : -1e30f;
        v.w = (kk + 3 < vl) ? v.w : -1e30f;
        v4[i] = v;
        mx = fmaxf(mx, fmaxf(fmaxf(v.x, v.y), fmaxf(v.z, v.w)));
    }
    #pragma unroll
    for (int o = 16; o; o >>= 1) mx = fmaxf(mx, __shfl_xor_sync(0xffffffffu, mx, o));

    float sum = 0.f;
    #pragma unroll
    for (int i = 0; i < 8; i++) {
        float4 v = v4[i];
        v.x = (v.x > -1e29f) ? __expf(v.x - mx) : 0.f;
        v.y = (v.y > -1e29f) ? __expf(v.y - mx) : 0.f;
        v.z = (v.z > -1e29f) ? __expf(v.z - mx) : 0.f;
        v.w = (v.w > -1e29f) ? __expf(v.w - mx) : 0.f;
        v4[i] = v;
        sum += (v.x + v.y) + (v.z + v.w);
    }
    #pragma unroll
    for (int o = 16; o; o >>= 1) sum += __shfl_xor_sync(0xffffffffu, sum, o);

    float r = 1.f / sum;
    #pragma unroll
    for (int i = 0; i < 8; i++) {
        float4 v = v4[i];
        v.x *= r; v.y *= r; v.z *= r; v.w *= r;
        ((float4*)s)[lane + i * 32] = v;
    }
}

// ---------------------------------------------------------------------------
// AV GEMM split-K (measured-best fp32 config: 256 thr, 4x4/thread, pipelined)
// ---------------------------------------------------------------------------
struct GemmSmem {
    float As[2][16][68];
    float Bs[2][16][68];
};

__global__ __launch_bounds__(256) void av_gemm(
    const float* __restrict__ V, const int* __restrict__ vlen)
{
    const int bz = blockIdx.z;
    const int b  = bz >> 3;
    const int s  = bz & 7;
    const int m0 = blockIdx.x * 64;
    const int n0 = blockIdx.y * 64;
    const int vl = vlen[b];
    const int kcap = min(KN, (vl + 15) & ~15);

    const int kbeg = s * KSPLIT;
    const int kend = min(kbeg + KSPLIT, kcap);
    if (kbeg >= kend) return;

    const float* __restrict__ A  = g_scores + (size_t)b * QN * KN;
    const float* __restrict__ Bv = V + (size_t)b * KN * DD;
    float* __restrict__ C        = g_avp[s] + (size_t)b * QN * DD;

    __shared__ __align__(16) GemmSmem sm;

    const int tid = threadIdx.x;
    const int tx = tid & 15;
    const int ty = tid >> 4;
    const int arow = tid >> 2;
    const int ac4  = tid & 3;
    const int bn4  = tid & 15;
    const int bkk  = tid >> 4;

    const int ntile = (kend - kbeg) >> 4;

    float acc[4][4] = {};
    float4 pa, pb;

    pa = *(const float4*)&A[(size_t)(m0 + arow) * KN + kbeg + ac4 * 4];
    pb = *(const float4*)&Bv[(size_t)(kbeg + bkk) * DD + n0 + bn4 * 4];
    sm.As[0][ac4 * 4 + 0][arow] = pa.x;
    sm.As[0][ac4 * 4 + 1][arow] = pa.y;
    sm.As[0][ac4 * 4 + 2][arow] = pa.z;
    sm.As[0][ac4 * 4 + 3][arow] = pa.w;
    *(float4*)&sm.Bs[0][bkk][bn4 * 4] = pb;
    __syncthreads();

    int buf = 0;
    for (int t = 0; t < ntile; t++) {
        if (t + 1 < ntile) {
            int k0 = kbeg + (t + 1) * 16;
            pa = *(const float4*)&A[(size_t)(m0 + arow) * KN + k0 + ac4 * 4];
            pb = *(const float4*)&Bv[(size_t)(k0 + bkk) * DD + n0 + bn4 * 4];
        }
        #pragma unroll
        for (int kk = 0; kk < 16; kk++) {
            float4 a = *(const float4*)&sm.As[buf][kk][ty * 4];
            float4 bq = *(const float4*)&sm.Bs[buf][kk][tx * 4];
            float av[4] = {a.x, a.y, a.z, a.w};
            float bv2[4] = {bq.x, bq.y, bq.z, bq.w};
            #pragma unroll
            for (int i = 0; i < 4; i++)
                #pragma unroll
                for (int j = 0; j < 4; j++)
                    acc[i][j] = fmaf(av[i], bv2[j], acc[i][j]);
        }
        if (t + 1 < ntile) {
            int nb = buf ^ 1;
            sm.As[nb][ac4 * 4 + 0][arow] = pa.x;
            sm.As[nb][ac4 * 4 + 1][arow] = pa.y;
            sm.As[nb][ac4 * 4 + 2][arow] = pa.z;
            sm.As[nb][ac4 * 4 + 3][arow] = pa.w;
            *(float4*)&sm.Bs[nb][bkk][bn4 * 4] = pb;
            __syncthreads();
            buf = nb;
        }
    }

    #pragma unroll
    for (int i = 0; i < 4; i++) {
        float4 o = make_float4(acc[i][0], acc[i][1], acc[i][2], acc[i][3]);
        *(float4*)&C[(size_t)(m0 + ty * 4 + i) * DD + n0 + tx * 4] = o;
    }
}

// ---------------------------------------------------------------------------
// Reduce AV split-K partials into out.
// ---------------------------------------------------------------------------
__global__ __launch_bounds__(256) void av_reduce(
    float* __restrict__ out, const int* __restrict__ vlen)
{
    const int idx = blockIdx.x * 256 + threadIdx.x;
    const int perB = QN * DD / 4;
    const int b = idx / perB;
    const int vl = vlen[b];
    const int ns = min(NSPLIT, (vl + KSPLIT - 1) / KSPLIT);

    float4 acc = ((const float4*)g_avp[0])[idx];
    for (int s = 1; s < ns; s++) {
        float4 p = ((const float4*)g_avp[s])[idx];
        acc.x += p.x; acc.y += p.y; acc.z += p.z; acc.w += p.w;
    }
    ((float4*)out)[idx] = acc;
}

// ---------------------------------------------------------------------------
extern "C" void kernel_launch(void* const* d_in, const int* in_sizes, int n_in,
                              void* d_out, int out_size)
{
    (void)in_sizes; (void)n_in; (void)out_size;
    const float* queries = (const float*)d_in[0];   // [4,128,512]
    const float* keys    = (const float*)d_in[1];   // [4,1024,512]
    const float* values  = (const float*)d_in[2];   // [4,1024,512]
    const int*   vlen    = (const int*)d_in[3];     // [4]
    const float* Wq      = (const float*)d_in[4];   // [512,256]
    const float* Wk      = (const float*)d_in[5];   // [512,256]
    const float* wv      = (const float*)d_in[6];   // [256]
    float* out = (float*)d_out;                     // [4,128,512]

    static bool attr_set = false;
    if (!attr_set) {
        cudaFuncSetAttribute(proj_hmma,
                             cudaFuncAttributeMaxDynamicSharedMemorySize,
                             PROJ_SMEM);
        attr_set = true;
    }

    conv_ab<<<2304, 256>>>(queries, keys);
    conv_w<<<dim3(16, 8, 2), 256>>>(Wq, Wk);
    proj_hmma<<<dim3(36, 4), 512, PROJ_SMEM>>>(vlen);
    scores_kernel<<<dim3(16, 8, 4), 512>>>(wv, vlen);
    softmax_kernel<<<128, 128>>>(vlen);
    av_gemm<<<dim3(2, 8, BB * NSPLIT), 256>>>(values, vlen);
    av_reduce<<<256, 256>>>(out, vlen);
}